// round 16
// baseline (speedup 1.0000x reference)
#include <cuda_runtime.h>
#include <cuda_bf16.h>
#include <mma.h>
#include <math.h>

using namespace nvcuda;

// ---------------------------------------------------------------------------
// Problem constants
// ---------------------------------------------------------------------------
#define Bv   8
#define Tv   1024
#define Fv   64
#define DMv  256
#define Lv   4
#define DIv  512          // 2*DM
#define Nv   16
#define DCv  4
#define DTRv 16           // DM/16
#define BT   (Bv*Tv)      // 8192
#define NCH  8            // scan chunks
#define CHT  128          // timesteps per chunk

// ---------------------------------------------------------------------------
// Scratch (device globals; no runtime allocation allowed)
// ---------------------------------------------------------------------------
__device__ float g_h   [BT * DMv];
__device__ float g_xz  [BT * (2*DIv)];
__device__ float g_xc  [BT * DIv];
__device__ float g_dt  [BT * DIv];
__device__ float g_BC  [BT * (2*Nv)];
__device__ float g_y   [BT * DIv];

__device__ float g_chP[Bv * DIv * Nv * NCH];
__device__ float g_chH[Bv * DIv * Nv * NCH];

// split-bf16 weights: proj[16384] | ipw[1048576] | opw[524288] | xpw_pad[131072]
#define W_PROJ 0
#define W_IPW  16384
#define W_OPW  1064960
#define W_XPW  1589248
__device__ __nv_bfloat16 g_whi[1720320];
__device__ __nv_bfloat16 g_wlo[1720320];

// ---------------------------------------------------------------------------
// One-shot weight split (proj | ipw | opw | padded xpw).  grid 1680 x 256.
// ---------------------------------------------------------------------------
__global__ void __launch_bounds__(256)
split_all_kernel(const float* __restrict__ proj_w,
                 const float* __restrict__ ipw,
                 const float* __restrict__ opw,
                 const float* __restrict__ xpw,
                 __nv_bfloat16* __restrict__ whi,
                 __nv_bfloat16* __restrict__ wlo)
{
    const int i = blockIdx.x * 256 + threadIdx.x;
    float4 v;
    int dst_el;
    if (i < 4096) {
        v = *(const float4*)(proj_w + i*4);
        dst_el = W_PROJ + i*4;
    } else if (i < 266240) {
        const int j = i - 4096;
        v = *(const float4*)(ipw + (size_t)j*4);
        dst_el = W_IPW + j*4;
    } else if (i < 397312) {
        const int j = i - 266240;
        v = *(const float4*)(opw + (size_t)j*4);
        dst_el = W_OPW + j*4;
    } else if (i < 430080) {
        const int j  = i - 397312;
        const int el = j * 4;
        const int l  = el >> 15;
        const int rm = el & 32767;
        const int o  = rm >> 9;
        const int k  = rm & 511;
        if (o < 48) v = *(const float4*)(xpw + (size_t)l*48*512 + o*512 + k);
        else        { v.x = 0.f; v.y = 0.f; v.z = 0.f; v.w = 0.f; }
        dst_el = W_XPW + el;
    } else return;

    __nv_bfloat16* hi = whi + dst_el;
    __nv_bfloat16* lo = wlo + dst_el;
    __nv_bfloat16 h0 = __float2bfloat16(v.x);
    __nv_bfloat16 h1 = __float2bfloat16(v.y);
    __nv_bfloat16 h2 = __float2bfloat16(v.z);
    __nv_bfloat16 h3 = __float2bfloat16(v.w);
    hi[0] = h0; hi[1] = h1; hi[2] = h2; hi[3] = h3;
    lo[0] = __float2bfloat16(v.x - __bfloat162float(h0));
    lo[1] = __float2bfloat16(v.y - __bfloat162float(h1));
    lo[2] = __float2bfloat16(v.z - __bfloat162float(h2));
    lo[3] = __float2bfloat16(v.w - __bfloat162float(h3));
}

// ---------------------------------------------------------------------------
// Tensor-core GEMM (BM=64, BN=128) — input proj and out_proj.
// ---------------------------------------------------------------------------
#define SPAD 40

__global__ void __launch_bounds__(256, 2)
wgemm_nt_kernel(const float* __restrict__ A, const float* __restrict__ Abias,
                const __nv_bfloat16* __restrict__ Whi,
                const __nv_bfloat16* __restrict__ Wlo,
                float* __restrict__ C,
                int M, int N, int K)
{
    __shared__ __align__(16) __nv_bfloat16 Ah[64*SPAD];
    __shared__ __align__(16) __nv_bfloat16 Al[64*SPAD];
    __shared__ __align__(16) __nv_bfloat16 Bh[128*SPAD];
    __shared__ __align__(16) __nv_bfloat16 Bl[128*SPAD];

    const int tid = threadIdx.x;
    const int bm  = blockIdx.y, bn = blockIdx.x;
    const int wid = tid >> 5;
    const int wm  = wid >> 2;
    const int wn  = wid & 3;

    wmma::fragment<wmma::accumulator, 16, 16, 16, float> acc[2][2];
#pragma unroll
    for (int mi = 0; mi < 2; ++mi)
#pragma unroll
        for (int ni = 0; ni < 2; ++ni)
            wmma::fill_fragment(acc[mi][ni], 0.0f);

    for (int k0 = 0; k0 < K; k0 += 32) {
#pragma unroll
        for (int i = 0; i < 2; ++i) {
            const int idx = tid + i * 256;
            const int row = idx >> 3;
            const int kc  = (idx & 7) << 2;
            float4 v = *(const float4*)(A + (size_t)(bm*64 + row) * K + k0 + kc);
            if (Abias) {
                const float4 bb = *(const float4*)(Abias + k0 + kc);
                v.x += bb.x; v.y += bb.y; v.z += bb.z; v.w += bb.w;
            }
            __nv_bfloat16 h0 = __float2bfloat16(v.x);
            __nv_bfloat16 h1 = __float2bfloat16(v.y);
            __nv_bfloat16 h2 = __float2bfloat16(v.z);
            __nv_bfloat16 h3 = __float2bfloat16(v.w);
            __nv_bfloat162 ph0; ph0.x = h0; ph0.y = h1;
            __nv_bfloat162 ph1; ph1.x = h2; ph1.y = h3;
            *(__nv_bfloat162*)(Ah + row*SPAD + kc)     = ph0;
            *(__nv_bfloat162*)(Ah + row*SPAD + kc + 2) = ph1;
            __nv_bfloat162 pl0; pl0.x = __float2bfloat16(v.x - __bfloat162float(h0));
                                pl0.y = __float2bfloat16(v.y - __bfloat162float(h1));
            __nv_bfloat162 pl1; pl1.x = __float2bfloat16(v.z - __bfloat162float(h2));
                                pl1.y = __float2bfloat16(v.w - __bfloat162float(h3));
            *(__nv_bfloat162*)(Al + row*SPAD + kc)     = pl0;
            *(__nv_bfloat162*)(Al + row*SPAD + kc + 2) = pl1;
        }
#pragma unroll
        for (int i = 0; i < 2; ++i) {
            const int idx = tid + i * 256;
            const int row = idx >> 2;
            const int kc  = (idx & 3) << 3;
            const size_t g = (size_t)(bn*128 + row) * K + k0 + kc;
            *(float4*)(Bh + row*SPAD + kc) = *(const float4*)(Whi + g);
            *(float4*)(Bl + row*SPAD + kc) = *(const float4*)(Wlo + g);
        }
        __syncthreads();

#pragma unroll
        for (int ks = 0; ks < 32; ks += 16) {
            wmma::fragment<wmma::matrix_b, 16, 16, 16, __nv_bfloat16, wmma::col_major> bH[2], bL[2];
#pragma unroll
            for (int ni = 0; ni < 2; ++ni) {
                const int rr = wn*32 + ni*16;
                wmma::load_matrix_sync(bH[ni], Bh + rr*SPAD + ks, SPAD);
                wmma::load_matrix_sync(bL[ni], Bl + rr*SPAD + ks, SPAD);
            }
#pragma unroll
            for (int mi = 0; mi < 2; ++mi) {
                wmma::fragment<wmma::matrix_a, 16, 16, 16, __nv_bfloat16, wmma::row_major> aH, aL;
                const int rr = wm*32 + mi*16;
                wmma::load_matrix_sync(aH, Ah + rr*SPAD + ks, SPAD);
                wmma::load_matrix_sync(aL, Al + rr*SPAD + ks, SPAD);
#pragma unroll
                for (int ni = 0; ni < 2; ++ni) {
                    wmma::mma_sync(acc[mi][ni], aH, bH[ni], acc[mi][ni]);
                    wmma::mma_sync(acc[mi][ni], aH, bL[ni], acc[mi][ni]);
                    wmma::mma_sync(acc[mi][ni], aL, bH[ni], acc[mi][ni]);
                }
            }
        }
        __syncthreads();
    }

#pragma unroll
    for (int mi = 0; mi < 2; ++mi)
#pragma unroll
        for (int ni = 0; ni < 2; ++ni) {
            const int rr = bm*64 + wm*32 + mi*16;
            const int cc = bn*128 + wn*32 + ni*16;
            wmma::store_matrix_sync(C + (size_t)rr * N + cc, acc[mi][ni], N,
                                    wmma::mem_row_major);
        }
}

// ---------------------------------------------------------------------------
// Big-tile GEMM for in_proj (BM=128, BN=128; unchanged from R15).
// ---------------------------------------------------------------------------
__global__ void __launch_bounds__(256, 2)
wgemm_ip_kernel(const float* __restrict__ A, const float* __restrict__ Abias,
                const __nv_bfloat16* __restrict__ Whi,
                const __nv_bfloat16* __restrict__ Wlo,
                float* __restrict__ C,
                int M, int N, int K)
{
    __shared__ __align__(16) __nv_bfloat16 Ah[128*SPAD];
    __shared__ __align__(16) __nv_bfloat16 Al[128*SPAD];
    __shared__ __align__(16) __nv_bfloat16 Bh[128*SPAD];
    __shared__ __align__(16) __nv_bfloat16 Bl[128*SPAD];

    const int tid = threadIdx.x;
    const int bm  = blockIdx.y, bn = blockIdx.x;
    const int wid = tid >> 5;
    const int wm  = wid >> 1;
    const int wn  = wid & 1;

    wmma::fragment<wmma::accumulator, 16, 16, 16, float> acc[2][4];
#pragma unroll
    for (int mi = 0; mi < 2; ++mi)
#pragma unroll
        for (int ni = 0; ni < 4; ++ni)
            wmma::fill_fragment(acc[mi][ni], 0.0f);

    for (int k0 = 0; k0 < K; k0 += 32) {
#pragma unroll
        for (int i = 0; i < 4; ++i) {
            const int idx = tid + i * 256;
            const int row = idx >> 3;
            const int kc  = (idx & 7) << 2;
            float4 v = *(const float4*)(A + (size_t)(bm*128 + row) * K + k0 + kc);
            if (Abias) {
                const float4 bb = *(const float4*)(Abias + k0 + kc);
                v.x += bb.x; v.y += bb.y; v.z += bb.z; v.w += bb.w;
            }
            __nv_bfloat16 h0 = __float2bfloat16(v.x);
            __nv_bfloat16 h1 = __float2bfloat16(v.y);
            __nv_bfloat16 h2 = __float2bfloat16(v.z);
            __nv_bfloat16 h3 = __float2bfloat16(v.w);
            __nv_bfloat162 ph0; ph0.x = h0; ph0.y = h1;
            __nv_bfloat162 ph1; ph1.x = h2; ph1.y = h3;
            *(__nv_bfloat162*)(Ah + row*SPAD + kc)     = ph0;
            *(__nv_bfloat162*)(Ah + row*SPAD + kc + 2) = ph1;
            __nv_bfloat162 pl0; pl0.x = __float2bfloat16(v.x - __bfloat162float(h0));
                                pl0.y = __float2bfloat16(v.y - __bfloat162float(h1));
            __nv_bfloat162 pl1; pl1.x = __float2bfloat16(v.z - __bfloat162float(h2));
                                pl1.y = __float2bfloat16(v.w - __bfloat162float(h3));
            *(__nv_bfloat162*)(Al + row*SPAD + kc)     = pl0;
            *(__nv_bfloat162*)(Al + row*SPAD + kc + 2) = pl1;
        }
#pragma unroll
        for (int i = 0; i < 2; ++i) {
            const int idx = tid + i * 256;
            const int row = idx >> 2;
            const int kc  = (idx & 3) << 3;
            const size_t g = (size_t)(bn*128 + row) * K + k0 + kc;
            *(float4*)(Bh + row*SPAD + kc) = *(const float4*)(Whi + g);
            *(float4*)(Bl + row*SPAD + kc) = *(const float4*)(Wlo + g);
        }
        __syncthreads();

#pragma unroll
        for (int ks = 0; ks < 32; ks += 16) {
            wmma::fragment<wmma::matrix_a, 16, 16, 16, __nv_bfloat16, wmma::row_major> aH[2], aL[2];
#pragma unroll
            for (int mi = 0; mi < 2; ++mi) {
                const int rr = wm*32 + mi*16;
                wmma::load_matrix_sync(aH[mi], Ah + rr*SPAD + ks, SPAD);
                wmma::load_matrix_sync(aL[mi], Al + rr*SPAD + ks, SPAD);
            }
#pragma unroll
            for (int ni = 0; ni < 4; ++ni) {
                wmma::fragment<wmma::matrix_b, 16, 16, 16, __nv_bfloat16, wmma::col_major> bH, bL;
                const int rr = wn*64 + ni*16;
                wmma::load_matrix_sync(bH, Bh + rr*SPAD + ks, SPAD);
                wmma::load_matrix_sync(bL, Bl + rr*SPAD + ks, SPAD);
#pragma unroll
                for (int mi = 0; mi < 2; ++mi) {
                    wmma::mma_sync(acc[mi][ni], aH[mi], bH, acc[mi][ni]);
                    wmma::mma_sync(acc[mi][ni], aH[mi], bL, acc[mi][ni]);
                    wmma::mma_sync(acc[mi][ni], aL[mi], bH, acc[mi][ni]);
                }
            }
        }
        __syncthreads();
    }

#pragma unroll
    for (int mi = 0; mi < 2; ++mi)
#pragma unroll
        for (int ni = 0; ni < 4; ++ni) {
            const int rr = bm*128 + wm*32 + mi*16;
            const int cc = bn*128 + wn*64 + ni*16;
            wmma::store_matrix_sync(C + (size_t)rr * N + cc, acc[mi][ni], N,
                                    wmma::mem_row_major);
        }
}

// ---------------------------------------------------------------------------
// FUSED: conv(4)+SiLU  ->  x_proj GEMM (BN=64)  ->  dt_proj/softplus + B/C.
// A-staging reads raw g_xz (67-row halo tile), computes conv+SiLU in-kernel,
// writes fp32 xc to g_xc (for scan), and splits to bf16 hi/lo for the MMA.
// grid (1, 128), 256 threads, 2 blocks/SM.
// ---------------------------------------------------------------------------
__global__ void __launch_bounds__(256, 2)
xproj_dt_kernel(const __nv_bfloat16* __restrict__ Whi,
                const __nv_bfloat16* __restrict__ Wlo,
                const float* __restrict__ conv_w,
                const float* __restrict__ conv_b,
                const float* __restrict__ dtw,
                const float* __restrict__ dtb)
{
    __shared__ __align__(16) __nv_bfloat16 Ah[64*SPAD];
    __shared__ __align__(16) __nv_bfloat16 Al[64*SPAD];
    __shared__ __align__(16) __nv_bfloat16 Bh[64*SPAD];
    __shared__ __align__(16) __nv_bfloat16 Bl[64*SPAD];
    __shared__ __align__(16) float xs[67][33];     // raw xz tile + halo
    __shared__ __align__(16) float scw[32][4];     // conv weights (k-chunk)
    __shared__ float scb[32];
    __shared__ __align__(16) float xdbl_s[64][68];

    const int tid  = threadIdx.x;
    const int bm   = blockIdx.y;          // 0..127
    const int row0 = bm * 64;             // global row (64 | 1024: same batch)
    const int b    = row0 >> 10;
    const int t0   = row0 & 1023;
    const int wid  = tid >> 5;
    const int wm   = wid >> 1;
    const int wn   = wid & 1;
    const int K    = DIv;

    wmma::fragment<wmma::accumulator, 16, 16, 16, float> acc[2];
    wmma::fill_fragment(acc[0], 0.0f);
    wmma::fill_fragment(acc[1], 0.0f);

    for (int k0 = 0; k0 < K; k0 += 32) {
        // ---- stage raw xz rows t0-3..t0+63, channels k0..k0+31 --------------
        for (int idx = tid; idx < 67 * 8; idx += 256) {
            const int r  = idx >> 3;              // 0..66
            const int c4 = idx & 7;
            const int t  = t0 - 3 + r;
            float4 v;
            if (t >= 0) v = *(const float4*)(g_xz + (size_t)(b*Tv + t) * (2*DIv) + k0 + c4*4);
            else        { v.x = 0.f; v.y = 0.f; v.z = 0.f; v.w = 0.f; }
            xs[r][c4*4 + 0] = v.x;
            xs[r][c4*4 + 1] = v.y;
            xs[r][c4*4 + 2] = v.z;
            xs[r][c4*4 + 3] = v.w;
        }
        // conv weights + bias for this channel chunk
        if (tid < 32) {
            const float4 w = *(const float4*)(conv_w + (k0 + tid) * 4);
            scw[tid][0] = w.x; scw[tid][1] = w.y;
            scw[tid][2] = w.z; scw[tid][3] = w.w;
            scb[tid] = conv_b[k0 + tid];
        }
        // ---- stage W (pre-split bf16) ---------------------------------------
        {
            const int row = tid >> 2;
            const int kc  = (tid & 3) << 3;
            const size_t g = (size_t)row * K + k0 + kc;
            *(float4*)(Bh + row*SPAD + kc) = *(const float4*)(Whi + g);
            *(float4*)(Bl + row*SPAD + kc) = *(const float4*)(Wlo + g);
        }
        __syncthreads();

        // ---- conv + SiLU -> xc (global + hi/lo smem) -------------------------
#pragma unroll
        for (int i = 0; i < 2; ++i) {
            const int idx = tid + i * 256;        // 0..511
            const int r   = idx >> 3;             // 0..63
            const int c4  = idx & 7;
            float out[4];
#pragma unroll
            for (int j = 0; j < 4; ++j) {
                const int c = c4*4 + j;
                const float s = scw[c][0]*xs[r][c]   + scw[c][1]*xs[r+1][c]
                              + scw[c][2]*xs[r+2][c] + scw[c][3]*xs[r+3][c]
                              + scb[c];
                out[j] = s / (1.f + __expf(-s));
            }
            float4 o4; o4.x = out[0]; o4.y = out[1]; o4.z = out[2]; o4.w = out[3];
            *(float4*)(g_xc + (size_t)(row0 + r) * DIv + k0 + c4*4) = o4;

            const int kc = c4 * 4;
            __nv_bfloat16 h0 = __float2bfloat16(out[0]);
            __nv_bfloat16 h1 = __float2bfloat16(out[1]);
            __nv_bfloat16 h2 = __float2bfloat16(out[2]);
            __nv_bfloat16 h3 = __float2bfloat16(out[3]);
            __nv_bfloat162 ph0; ph0.x = h0; ph0.y = h1;
            __nv_bfloat162 ph1; ph1.x = h2; ph1.y = h3;
            *(__nv_bfloat162*)(Ah + r*SPAD + kc)     = ph0;
            *(__nv_bfloat162*)(Ah + r*SPAD + kc + 2) = ph1;
            __nv_bfloat162 pl0; pl0.x = __float2bfloat16(out[0] - __bfloat162float(h0));
                                pl0.y = __float2bfloat16(out[1] - __bfloat162float(h1));
            __nv_bfloat162 pl1; pl1.x = __float2bfloat16(out[2] - __bfloat162float(h2));
                                pl1.y = __float2bfloat16(out[3] - __bfloat162float(h3));
            *(__nv_bfloat162*)(Al + r*SPAD + kc)     = pl0;
            *(__nv_bfloat162*)(Al + r*SPAD + kc + 2) = pl1;
        }
        __syncthreads();

        // ---- MMA --------------------------------------------------------------
#pragma unroll
        for (int ks = 0; ks < 32; ks += 16) {
            wmma::fragment<wmma::matrix_b, 16, 16, 16, __nv_bfloat16, wmma::col_major> bH[2], bL[2];
#pragma unroll
            for (int ni = 0; ni < 2; ++ni) {
                const int rr = wn*32 + ni*16;
                wmma::load_matrix_sync(bH[ni], Bh + rr*SPAD + ks, SPAD);
                wmma::load_matrix_sync(bL[ni], Bl + rr*SPAD + ks, SPAD);
            }
            wmma::fragment<wmma::matrix_a, 16, 16, 16, __nv_bfloat16, wmma::row_major> aH, aL;
            wmma::load_matrix_sync(aH, Ah + (wm*16)*SPAD + ks, SPAD);
            wmma::load_matrix_sync(aL, Al + (wm*16)*SPAD + ks, SPAD);
#pragma unroll
            for (int ni = 0; ni < 2; ++ni) {
                wmma::mma_sync(acc[ni], aH, bH[ni], acc[ni]);
                wmma::mma_sync(acc[ni], aH, bL[ni], acc[ni]);
                wmma::mma_sync(acc[ni], aL, bH[ni], acc[ni]);
            }
        }
        __syncthreads();
    }

    // ---- epilogue: xdbl tile -> smem ----------------------------------------
#pragma unroll
    for (int ni = 0; ni < 2; ++ni)
        wmma::store_matrix_sync(&xdbl_s[wm*16][wn*32 + ni*16], acc[ni], 68,
                                wmma::mem_row_major);
    __syncthreads();

    // ---- B/C extraction -------------------------------------------------------
    {
        int idx = tid;
#pragma unroll
        for (int r = 0; r < 8; ++r, idx += 256) {
            const int tt = idx >> 5, c = idx & 31;
            g_BC[((size_t)(row0 + tt)) * (2*Nv) + c] = xdbl_s[tt][16 + c];
        }
    }

    // ---- dt_proj + softplus ---------------------------------------------------
    {
        const int d0 = tid, d1 = tid + 256;
        float w0[16], w1[16];
        *(float4*)&w0[0]  = *(const float4*)(dtw + d0*16 + 0);
        *(float4*)&w0[4]  = *(const float4*)(dtw + d0*16 + 4);
        *(float4*)&w0[8]  = *(const float4*)(dtw + d0*16 + 8);
        *(float4*)&w0[12] = *(const float4*)(dtw + d0*16 + 12);
        *(float4*)&w1[0]  = *(const float4*)(dtw + d1*16 + 0);
        *(float4*)&w1[4]  = *(const float4*)(dtw + d1*16 + 4);
        *(float4*)&w1[8]  = *(const float4*)(dtw + d1*16 + 8);
        *(float4*)&w1[12] = *(const float4*)(dtw + d1*16 + 12);
        const float b0 = dtb[d0], b1 = dtb[d1];

        for (int r = 0; r < 64; ++r) {
            float xv[16];
            *(float4*)&xv[0]  = *(const float4*)&xdbl_s[r][0];
            *(float4*)&xv[4]  = *(const float4*)&xdbl_s[r][4];
            *(float4*)&xv[8]  = *(const float4*)&xdbl_s[r][8];
            *(float4*)&xv[12] = *(const float4*)&xdbl_s[r][12];
            float s0 = b0, s1 = b1;
#pragma unroll
            for (int k = 0; k < 16; ++k) {
                s0 += xv[k] * w0[k];
                s1 += xv[k] * w1[k];
            }
            const float sp0 = fmaxf(s0, 0.f) + log1pf(__expf(-fabsf(s0)));
            const float sp1 = fmaxf(s1, 0.f) + log1pf(__expf(-fabsf(s1)));
            const size_t o = ((size_t)(row0 + r)) * DIv;
            g_dt[o + d0] = sp0;
            g_dt[o + d1] = sp1;
        }
    }
}

// ---------------------------------------------------------------------------
// Scan v3 pass 1 (unchanged).  grid (4, 8, 7), 128 threads.
// ---------------------------------------------------------------------------
__global__ void __launch_bounds__(128)
scan_pass1_kernel(const float* __restrict__ A_log)
{
    __shared__ __align__(16) float s_b[64][16];

    const int tid = threadIdx.x;
    const int d   = blockIdx.x * 128 + tid;
    const int b   = blockIdx.y;
    const int ch  = blockIdx.z;

    float a[16];
    {
        float4 v0 = *(const float4*)(A_log + d*16 + 0);
        float4 v1 = *(const float4*)(A_log + d*16 + 4);
        float4 v2 = *(const float4*)(A_log + d*16 + 8);
        float4 v3 = *(const float4*)(A_log + d*16 + 12);
        a[0]=-__expf(v0.x); a[1]=-__expf(v0.y); a[2]=-__expf(v0.z); a[3]=-__expf(v0.w);
        a[4]=-__expf(v1.x); a[5]=-__expf(v1.y); a[6]=-__expf(v1.z); a[7]=-__expf(v1.w);
        a[8]=-__expf(v2.x); a[9]=-__expf(v2.y); a[10]=-__expf(v2.z); a[11]=-__expf(v2.w);
        a[12]=-__expf(v3.x); a[13]=-__expf(v3.y); a[14]=-__expf(v3.z); a[15]=-__expf(v3.w);
    }

    float h[16], P[16];
#pragma unroll
    for (int n = 0; n < 16; ++n) { h[n] = 0.f; P[n] = 1.f; }

    for (int sc = 0; sc < 2; ++sc) {
        const int base = b * Tv + ch * CHT + sc * 64;
#pragma unroll
        for (int i = 0; i < 8; ++i) {
            const int idx = tid + i * 128;
            const int t = idx >> 4, n = idx & 15;
            s_b[t][n] = g_BC[(size_t)(base + t) * (2*Nv) + n];
        }
        __syncthreads();

#pragma unroll 2
        for (int t = 0; t < 64; ++t) {
            const float dtv = g_dt[(size_t)(base + t) * DIv + d];
            const float uv  = g_xc[(size_t)(base + t) * DIv + d];
            const float dtu = dtv * uv;
            const float4 B0 = *(const float4*)&s_b[t][0];
            const float4 B1 = *(const float4*)&s_b[t][4];
            const float4 B2 = *(const float4*)&s_b[t][8];
            const float4 B3 = *(const float4*)&s_b[t][12];
            const float Bs[16] = {B0.x,B0.y,B0.z,B0.w, B1.x,B1.y,B1.z,B1.w,
                                  B2.x,B2.y,B2.z,B2.w, B3.x,B3.y,B3.z,B3.w};
#pragma unroll
            for (int n = 0; n < 16; ++n) {
                const float e = __expf(dtv * a[n]);
                h[n] = e * h[n] + dtu * Bs[n];
                P[n] *= e;
            }
        }
        __syncthreads();
    }

    const size_t o = (((size_t)b * DIv + d) * Nv) * NCH + ch;
#pragma unroll
    for (int n = 0; n < 16; ++n) {
        g_chP[o + n*NCH] = P[n];
        g_chH[o + n*NCH] = h[n];
    }
}

// ---------------------------------------------------------------------------
// Scan v3 pass 2 (unchanged).  grid (4, 8, 8), 128 threads.
// ---------------------------------------------------------------------------
__global__ void __launch_bounds__(128)
scan_pass2_kernel(const float* __restrict__ A_log, const float* __restrict__ Dp)
{
    __shared__ __align__(16) float s_bc[64][32];

    const int tid = threadIdx.x;
    const int d   = blockIdx.x * 128 + tid;
    const int b   = blockIdx.y;
    const int ch  = blockIdx.z;

    float a[16];
    {
        float4 v0 = *(const float4*)(A_log + d*16 + 0);
        float4 v1 = *(const float4*)(A_log + d*16 + 4);
        float4 v2 = *(const float4*)(A_log + d*16 + 8);
        float4 v3 = *(const float4*)(A_log + d*16 + 12);
        a[0]=-__expf(v0.x); a[1]=-__expf(v0.y); a[2]=-__expf(v0.z); a[3]=-__expf(v0.w);
        a[4]=-__expf(v1.x); a[5]=-__expf(v1.y); a[6]=-__expf(v1.z); a[7]=-__expf(v1.w);
        a[8]=-__expf(v2.x); a[9]=-__expf(v2.y); a[10]=-__expf(v2.z); a[11]=-__expf(v2.w);
        a[12]=-__expf(v3.x); a[13]=-__expf(v3.y); a[14]=-__expf(v3.z); a[15]=-__expf(v3.w);
    }
    const float dcoef = Dp[d];

    float h[16];
    {
        const size_t sb = (((size_t)b * DIv + d) * Nv) * NCH;
#pragma unroll
        for (int n = 0; n < 16; ++n) {
            float hh = 0.f;
            for (int c = 0; c < ch; ++c)
                hh = g_chP[sb + n*NCH + c] * hh + g_chH[sb + n*NCH + c];
            h[n] = hh;
        }
    }

    for (int sc = 0; sc < 2; ++sc) {
        const int base = b * Tv + ch * CHT + sc * 64;
#pragma unroll
        for (int i = 0; i < 16; ++i) {
            const int idx = tid + i * 128;
            const int t = idx >> 5, c = idx & 31;
            s_bc[t][c] = g_BC[(size_t)(base + t) * (2*Nv) + c];
        }
        __syncthreads();

#pragma unroll 2
        for (int t = 0; t < 64; ++t) {
            const float dtv = g_dt[(size_t)(base + t) * DIv + d];
            const float uv  = g_xc[(size_t)(base + t) * DIv + d];
            const float zv  = g_xz[(size_t)(base + t) * (2*DIv) + DIv + d];
            const float dtu = dtv * uv;
            const float4 B0 = *(const float4*)&s_bc[t][0];
            const float4 B1 = *(const float4*)&s_bc[t][4];
            const float4 B2 = *(const float4*)&s_bc[t][8];
            const float4 B3 = *(const float4*)&s_bc[t][12];
            const float4 C0 = *(const float4*)&s_bc[t][16];
            const float4 C1 = *(const float4*)&s_bc[t][20];
            const float4 C2 = *(const float4*)&s_bc[t][24];
            const float4 C3 = *(const float4*)&s_bc[t][28];
            const float Bs[16] = {B0.x,B0.y,B0.z,B0.w, B1.x,B1.y,B1.z,B1.w,
                                  B2.x,B2.y,B2.z,B2.w, B3.x,B3.y,B3.z,B3.w};
            const float Cs[16] = {C0.x,C0.y,C0.z,C0.w, C1.x,C1.y,C1.z,C1.w,
                                  C2.x,C2.y,C2.z,C2.w, C3.x,C3.y,C3.z,C3.w};
            float y = 0.f;
#pragma unroll
            for (int n = 0; n < 16; ++n) {
                const float e = __expf(dtv * a[n]);
                h[n] = e * h[n] + dtu * Bs[n];
                y += h[n] * Cs[n];
            }
            y += dcoef * uv;
            y *= zv / (1.f + __expf(-zv));
            g_y[(size_t)(base + t) * DIv + d] = y;
        }
        __syncthreads();
    }
}

// ---------------------------------------------------------------------------
// Final: LayerNorm(last token) + head.
// ---------------------------------------------------------------------------
__global__ void __launch_bounds__(256)
final_kernel(const float* __restrict__ ln_g, const float* __restrict__ ln_b,
             const float* __restrict__ head_w, const float* __restrict__ head_b,
             float* __restrict__ out)
{
    __shared__ float red[256];
    const int b = blockIdx.x, tid = threadIdx.x;
    const float v = g_h[((size_t)(b * Tv + (Tv - 1))) * DMv + tid];

    red[tid] = v; __syncthreads();
    for (int s = 128; s > 0; s >>= 1) { if (tid < s) red[tid] += red[tid + s]; __syncthreads(); }
    const float mu = red[0] * (1.f / DMv);
    __syncthreads();

    const float dv = v - mu;
    red[tid] = dv * dv; __syncthreads();
    for (int s = 128; s > 0; s >>= 1) { if (tid < s) red[tid] += red[tid + s]; __syncthreads(); }
    const float var = red[0] * (1.f / DMv);
    __syncthreads();

    const float hn = dv * rsqrtf(var + 1e-5f) * ln_g[tid] + ln_b[tid];
    red[tid] = hn * head_w[tid]; __syncthreads();
    for (int s = 128; s > 0; s >>= 1) { if (tid < s) red[tid] += red[tid + s]; __syncthreads(); }
    if (tid == 0) out[b] = red[0] + head_b[0];
}

// ---------------------------------------------------------------------------
// Host launcher
// ---------------------------------------------------------------------------
extern "C" void kernel_launch(void* const* d_in, const int* in_sizes, int n_in,
                              void* d_out, int out_size)
{
    const float* x      = (const float*)d_in[0];
    const float* proj_w = (const float*)d_in[1];
    const float* proj_b = (const float*)d_in[2];
    const float* ipw    = (const float*)d_in[3];
    const float* cw     = (const float*)d_in[4];
    const float* cb     = (const float*)d_in[5];
    const float* xpw    = (const float*)d_in[6];
    const float* dtw    = (const float*)d_in[7];
    const float* dtb    = (const float*)d_in[8];
    const float* A_log  = (const float*)d_in[9];
    const float* Dp     = (const float*)d_in[10];
    const float* opw    = (const float*)d_in[11];
    const float* ln_g   = (const float*)d_in[12];
    const float* ln_b   = (const float*)d_in[13];
    const float* head_w = (const float*)d_in[14];
    const float* head_b = (const float*)d_in[15];
    float* out = (float*)d_out;

    float *hbuf, *xzbuf, *ybuf;
    __nv_bfloat16 *whi, *wlo;
    cudaGetSymbolAddress((void**)&hbuf,  g_h);
    cudaGetSymbolAddress((void**)&xzbuf, g_xz);
    cudaGetSymbolAddress((void**)&ybuf,  g_y);
    cudaGetSymbolAddress((void**)&whi,   g_whi);
    cudaGetSymbolAddress((void**)&wlo,   g_wlo);

    // Launch 1: all weight splits.
    split_all_kernel<<<1680, 256>>>(proj_w, ipw, opw, xpw, whi, wlo);

    dim3 grid_in(2, 128);
    dim3 grid_ip(8, 64);
    dim3 grid_op(2, 128);
    dim3 grid_xp(1, 128);
    dim3 grid_p1(4, 8, 7);
    dim3 grid_p2(4, 8, 8);

    // Launch 2: input projection  h = x @ proj_w^T  [8192,256], K=64
    wgemm_nt_kernel<<<grid_in, 256>>>(x, (const float*)0,
                                      whi + W_PROJ, wlo + W_PROJ,
                                      hbuf, BT, DMv, Fv);

    for (int l = 0; l < Lv; ++l) {
        const size_t ipoff = (size_t)l * 262144;
        const size_t opoff = (size_t)l * 131072;
        const size_t xpoff = (size_t)l * 32768;
        const float* abias  = (l == 0) ? proj_b : (const float*)0;
        const float* alog_l = A_log + (size_t)l * DIv * Nv;

        // in_proj (big-tile): xz = (h+bias?) @ ipw^T  [8192,1024], K=256
        wgemm_ip_kernel<<<grid_ip, 256>>>(hbuf, abias,
                                          whi + W_IPW + ipoff, wlo + W_IPW + ipoff,
                                          xzbuf, BT, 2*DIv, DMv);

        // Launch 4 (profiled, l==0): fused conv + x_proj + dt_proj + B/C
        xproj_dt_kernel<<<grid_xp, 256>>>(whi + W_XPW + xpoff,
                                          wlo + W_XPW + xpoff,
                                          cw + (size_t)l * DIv * DCv,
                                          cb + (size_t)l * DIv,
                                          dtw + (size_t)l * DIv * DTRv,
                                          dtb + (size_t)l * DIv);

        scan_pass1_kernel<<<grid_p1, 128>>>(alog_l);
        scan_pass2_kernel<<<grid_p2, 128>>>(alog_l, Dp + (size_t)l * DIv);

        // out_proj: h = y @ opw^T   [8192,256], K=512
        wgemm_nt_kernel<<<grid_op, 256>>>(ybuf, (const float*)0,
                                          whi + W_OPW + opoff, wlo + W_OPW + opoff,
                                          hbuf, BT, DMv, DIv);
    }

    final_kernel<<<Bv, 256>>>(ln_g, ln_b, head_w, head_b, out);
}

// round 17
// speedup vs baseline: 1.1369x; 1.1369x over previous
#include <cuda_runtime.h>
#include <cuda_bf16.h>
#include <mma.h>
#include <math.h>

using namespace nvcuda;

// ---------------------------------------------------------------------------
// Problem constants
// ---------------------------------------------------------------------------
#define Bv   8
#define Tv   1024
#define Fv   64
#define DMv  256
#define Lv   4
#define DIv  512          // 2*DM
#define Nv   16
#define DCv  4
#define DTRv 16           // DM/16
#define BT   (Bv*Tv)      // 8192
#define NCH  8            // scan chunks
#define CHT  128          // timesteps per chunk

// ---------------------------------------------------------------------------
// Scratch (device globals; no runtime allocation allowed)
// ---------------------------------------------------------------------------
__device__ float g_h   [BT * DMv];
__device__ float g_xz  [BT * (2*DIv)];
__device__ float g_xc  [BT * DIv];
__device__ float g_dt  [BT * DIv];
__device__ float g_BC  [BT * (2*Nv)];
__device__ float g_y   [BT * DIv];

__device__ float g_chP[Bv * DIv * Nv * NCH];
__device__ float g_chH[Bv * DIv * Nv * NCH];

// split-bf16 weights: proj[16384] | ipw[1048576] | opw[524288] | xpw_pad[131072]
#define W_PROJ 0
#define W_IPW  16384
#define W_OPW  1064960
#define W_XPW  1589248
__device__ __nv_bfloat16 g_whi[1720320];
__device__ __nv_bfloat16 g_wlo[1720320];

// ---------------------------------------------------------------------------
// One-shot weight split (proj | ipw | opw | padded xpw).  grid 1680 x 256.
// ---------------------------------------------------------------------------
__global__ void __launch_bounds__(256)
split_all_kernel(const float* __restrict__ proj_w,
                 const float* __restrict__ ipw,
                 const float* __restrict__ opw,
                 const float* __restrict__ xpw,
                 __nv_bfloat16* __restrict__ whi,
                 __nv_bfloat16* __restrict__ wlo)
{
    const int i = blockIdx.x * 256 + threadIdx.x;
    float4 v;
    int dst_el;
    if (i < 4096) {
        v = *(const float4*)(proj_w + i*4);
        dst_el = W_PROJ + i*4;
    } else if (i < 266240) {
        const int j = i - 4096;
        v = *(const float4*)(ipw + (size_t)j*4);
        dst_el = W_IPW + j*4;
    } else if (i < 397312) {
        const int j = i - 266240;
        v = *(const float4*)(opw + (size_t)j*4);
        dst_el = W_OPW + j*4;
    } else if (i < 430080) {
        const int j  = i - 397312;
        const int el = j * 4;
        const int l  = el >> 15;
        const int rm = el & 32767;
        const int o  = rm >> 9;
        const int k  = rm & 511;
        if (o < 48) v = *(const float4*)(xpw + (size_t)l*48*512 + o*512 + k);
        else        { v.x = 0.f; v.y = 0.f; v.z = 0.f; v.w = 0.f; }
        dst_el = W_XPW + el;
    } else return;

    __nv_bfloat16* hi = whi + dst_el;
    __nv_bfloat16* lo = wlo + dst_el;
    __nv_bfloat16 h0 = __float2bfloat16(v.x);
    __nv_bfloat16 h1 = __float2bfloat16(v.y);
    __nv_bfloat16 h2 = __float2bfloat16(v.z);
    __nv_bfloat16 h3 = __float2bfloat16(v.w);
    hi[0] = h0; hi[1] = h1; hi[2] = h2; hi[3] = h3;
    lo[0] = __float2bfloat16(v.x - __bfloat162float(h0));
    lo[1] = __float2bfloat16(v.y - __bfloat162float(h1));
    lo[2] = __float2bfloat16(v.z - __bfloat162float(h2));
    lo[3] = __float2bfloat16(v.w - __bfloat162float(h3));
}

// ---------------------------------------------------------------------------
// Tensor-core GEMM (BM=64, BN=128) — input proj and out_proj.
// ---------------------------------------------------------------------------
#define SPAD 40

__global__ void __launch_bounds__(256, 2)
wgemm_nt_kernel(const float* __restrict__ A, const float* __restrict__ Abias,
                const __nv_bfloat16* __restrict__ Whi,
                const __nv_bfloat16* __restrict__ Wlo,
                float* __restrict__ C,
                int M, int N, int K)
{
    __shared__ __align__(16) __nv_bfloat16 Ah[64*SPAD];
    __shared__ __align__(16) __nv_bfloat16 Al[64*SPAD];
    __shared__ __align__(16) __nv_bfloat16 Bh[128*SPAD];
    __shared__ __align__(16) __nv_bfloat16 Bl[128*SPAD];

    const int tid = threadIdx.x;
    const int bm  = blockIdx.y, bn = blockIdx.x;
    const int wid = tid >> 5;
    const int wm  = wid >> 2;
    const int wn  = wid & 3;

    wmma::fragment<wmma::accumulator, 16, 16, 16, float> acc[2][2];
#pragma unroll
    for (int mi = 0; mi < 2; ++mi)
#pragma unroll
        for (int ni = 0; ni < 2; ++ni)
            wmma::fill_fragment(acc[mi][ni], 0.0f);

    for (int k0 = 0; k0 < K; k0 += 32) {
#pragma unroll
        for (int i = 0; i < 2; ++i) {
            const int idx = tid + i * 256;
            const int row = idx >> 3;
            const int kc  = (idx & 7) << 2;
            float4 v = *(const float4*)(A + (size_t)(bm*64 + row) * K + k0 + kc);
            if (Abias) {
                const float4 bb = *(const float4*)(Abias + k0 + kc);
                v.x += bb.x; v.y += bb.y; v.z += bb.z; v.w += bb.w;
            }
            __nv_bfloat16 h0 = __float2bfloat16(v.x);
            __nv_bfloat16 h1 = __float2bfloat16(v.y);
            __nv_bfloat16 h2 = __float2bfloat16(v.z);
            __nv_bfloat16 h3 = __float2bfloat16(v.w);
            __nv_bfloat162 ph0; ph0.x = h0; ph0.y = h1;
            __nv_bfloat162 ph1; ph1.x = h2; ph1.y = h3;
            *(__nv_bfloat162*)(Ah + row*SPAD + kc)     = ph0;
            *(__nv_bfloat162*)(Ah + row*SPAD + kc + 2) = ph1;
            __nv_bfloat162 pl0; pl0.x = __float2bfloat16(v.x - __bfloat162float(h0));
                                pl0.y = __float2bfloat16(v.y - __bfloat162float(h1));
            __nv_bfloat162 pl1; pl1.x = __float2bfloat16(v.z - __bfloat162float(h2));
                                pl1.y = __float2bfloat16(v.w - __bfloat162float(h3));
            *(__nv_bfloat162*)(Al + row*SPAD + kc)     = pl0;
            *(__nv_bfloat162*)(Al + row*SPAD + kc + 2) = pl1;
        }
#pragma unroll
        for (int i = 0; i < 2; ++i) {
            const int idx = tid + i * 256;
            const int row = idx >> 2;
            const int kc  = (idx & 3) << 3;
            const size_t g = (size_t)(bn*128 + row) * K + k0 + kc;
            *(float4*)(Bh + row*SPAD + kc) = *(const float4*)(Whi + g);
            *(float4*)(Bl + row*SPAD + kc) = *(const float4*)(Wlo + g);
        }
        __syncthreads();

#pragma unroll
        for (int ks = 0; ks < 32; ks += 16) {
            wmma::fragment<wmma::matrix_b, 16, 16, 16, __nv_bfloat16, wmma::col_major> bH[2], bL[2];
#pragma unroll
            for (int ni = 0; ni < 2; ++ni) {
                const int rr = wn*32 + ni*16;
                wmma::load_matrix_sync(bH[ni], Bh + rr*SPAD + ks, SPAD);
                wmma::load_matrix_sync(bL[ni], Bl + rr*SPAD + ks, SPAD);
            }
#pragma unroll
            for (int mi = 0; mi < 2; ++mi) {
                wmma::fragment<wmma::matrix_a, 16, 16, 16, __nv_bfloat16, wmma::row_major> aH, aL;
                const int rr = wm*32 + mi*16;
                wmma::load_matrix_sync(aH, Ah + rr*SPAD + ks, SPAD);
                wmma::load_matrix_sync(aL, Al + rr*SPAD + ks, SPAD);
#pragma unroll
                for (int ni = 0; ni < 2; ++ni) {
                    wmma::mma_sync(acc[mi][ni], aH, bH[ni], acc[mi][ni]);
                    wmma::mma_sync(acc[mi][ni], aH, bL[ni], acc[mi][ni]);
                    wmma::mma_sync(acc[mi][ni], aL, bH[ni], acc[mi][ni]);
                }
            }
        }
        __syncthreads();
    }

#pragma unroll
    for (int mi = 0; mi < 2; ++mi)
#pragma unroll
        for (int ni = 0; ni < 2; ++ni) {
            const int rr = bm*64 + wm*32 + mi*16;
            const int cc = bn*128 + wn*32 + ni*16;
            wmma::store_matrix_sync(C + (size_t)rr * N + cc, acc[mi][ni], N,
                                    wmma::mem_row_major);
        }
}

// ---------------------------------------------------------------------------
// Big-tile GEMM for in_proj (BM=128, BN=128; unchanged from R15).
// ---------------------------------------------------------------------------
__global__ void __launch_bounds__(256, 2)
wgemm_ip_kernel(const float* __restrict__ A, const float* __restrict__ Abias,
                const __nv_bfloat16* __restrict__ Whi,
                const __nv_bfloat16* __restrict__ Wlo,
                float* __restrict__ C,
                int M, int N, int K)
{
    __shared__ __align__(16) __nv_bfloat16 Ah[128*SPAD];
    __shared__ __align__(16) __nv_bfloat16 Al[128*SPAD];
    __shared__ __align__(16) __nv_bfloat16 Bh[128*SPAD];
    __shared__ __align__(16) __nv_bfloat16 Bl[128*SPAD];

    const int tid = threadIdx.x;
    const int bm  = blockIdx.y, bn = blockIdx.x;
    const int wid = tid >> 5;
    const int wm  = wid >> 1;
    const int wn  = wid & 1;

    wmma::fragment<wmma::accumulator, 16, 16, 16, float> acc[2][4];
#pragma unroll
    for (int mi = 0; mi < 2; ++mi)
#pragma unroll
        for (int ni = 0; ni < 4; ++ni)
            wmma::fill_fragment(acc[mi][ni], 0.0f);

    for (int k0 = 0; k0 < K; k0 += 32) {
#pragma unroll
        for (int i = 0; i < 4; ++i) {
            const int idx = tid + i * 256;
            const int row = idx >> 3;
            const int kc  = (idx & 7) << 2;
            float4 v = *(const float4*)(A + (size_t)(bm*128 + row) * K + k0 + kc);
            if (Abias) {
                const float4 bb = *(const float4*)(Abias + k0 + kc);
                v.x += bb.x; v.y += bb.y; v.z += bb.z; v.w += bb.w;
            }
            __nv_bfloat16 h0 = __float2bfloat16(v.x);
            __nv_bfloat16 h1 = __float2bfloat16(v.y);
            __nv_bfloat16 h2 = __float2bfloat16(v.z);
            __nv_bfloat16 h3 = __float2bfloat16(v.w);
            __nv_bfloat162 ph0; ph0.x = h0; ph0.y = h1;
            __nv_bfloat162 ph1; ph1.x = h2; ph1.y = h3;
            *(__nv_bfloat162*)(Ah + row*SPAD + kc)     = ph0;
            *(__nv_bfloat162*)(Ah + row*SPAD + kc + 2) = ph1;
            __nv_bfloat162 pl0; pl0.x = __float2bfloat16(v.x - __bfloat162float(h0));
                                pl0.y = __float2bfloat16(v.y - __bfloat162float(h1));
            __nv_bfloat162 pl1; pl1.x = __float2bfloat16(v.z - __bfloat162float(h2));
                                pl1.y = __float2bfloat16(v.w - __bfloat162float(h3));
            *(__nv_bfloat162*)(Al + row*SPAD + kc)     = pl0;
            *(__nv_bfloat162*)(Al + row*SPAD + kc + 2) = pl1;
        }
#pragma unroll
        for (int i = 0; i < 2; ++i) {
            const int idx = tid + i * 256;
            const int row = idx >> 2;
            const int kc  = (idx & 3) << 3;
            const size_t g = (size_t)(bn*128 + row) * K + k0 + kc;
            *(float4*)(Bh + row*SPAD + kc) = *(const float4*)(Whi + g);
            *(float4*)(Bl + row*SPAD + kc) = *(const float4*)(Wlo + g);
        }
        __syncthreads();

#pragma unroll
        for (int ks = 0; ks < 32; ks += 16) {
            wmma::fragment<wmma::matrix_a, 16, 16, 16, __nv_bfloat16, wmma::row_major> aH[2], aL[2];
#pragma unroll
            for (int mi = 0; mi < 2; ++mi) {
                const int rr = wm*32 + mi*16;
                wmma::load_matrix_sync(aH[mi], Ah + rr*SPAD + ks, SPAD);
                wmma::load_matrix_sync(aL[mi], Al + rr*SPAD + ks, SPAD);
            }
#pragma unroll
            for (int ni = 0; ni < 4; ++ni) {
                wmma::fragment<wmma::matrix_b, 16, 16, 16, __nv_bfloat16, wmma::col_major> bH, bL;
                const int rr = wn*64 + ni*16;
                wmma::load_matrix_sync(bH, Bh + rr*SPAD + ks, SPAD);
                wmma::load_matrix_sync(bL, Bl + rr*SPAD + ks, SPAD);
#pragma unroll
                for (int mi = 0; mi < 2; ++mi) {
                    wmma::mma_sync(acc[mi][ni], aH[mi], bH, acc[mi][ni]);
                    wmma::mma_sync(acc[mi][ni], aH[mi], bL, acc[mi][ni]);
                    wmma::mma_sync(acc[mi][ni], aL[mi], bH, acc[mi][ni]);
                }
            }
        }
        __syncthreads();
    }

#pragma unroll
    for (int mi = 0; mi < 2; ++mi)
#pragma unroll
        for (int ni = 0; ni < 4; ++ni) {
            const int rr = bm*128 + wm*32 + mi*16;
            const int cc = bn*128 + wn*64 + ni*16;
            wmma::store_matrix_sync(C + (size_t)rr * N + cc, acc[mi][ni], N,
                                    wmma::mem_row_major);
        }
}

// ---------------------------------------------------------------------------
// conv(4) + bias + SiLU v3: smem-staged, coalesced (R15 version).
// 512 blocks, 256 threads.
// ---------------------------------------------------------------------------
__global__ void __launch_bounds__(256)
conv_silu_kernel(const float* __restrict__ conv_w,
                 const float* __restrict__ conv_b)
{
    __shared__ __align__(16) float xs[19][DIv];

    const int blk = blockIdx.x;
    const int b   = blk >> 6;
    const int t0  = (blk & 63) << 4;
    const int tid = threadIdx.x;

    for (int idx = tid; idx < 19 * 128; idx += 256) {
        const int r  = idx >> 7;
        const int c4 = idx & 127;
        const int t  = t0 - 3 + r;
        float4 v;
        if (t >= 0) v = *(const float4*)(g_xz + (size_t)(b*Tv + t) * (2*DIv) + c4*4);
        else        { v.x = 0.f; v.y = 0.f; v.z = 0.f; v.w = 0.f; }
        *(float4*)&xs[r][c4*4] = v;
    }
    __syncthreads();

#pragma unroll
    for (int dd = 0; dd < 2; ++dd) {
        const int d = tid + dd * 256;
        const float4 cw4 = *(const float4*)(conv_w + d*4);
        const float  cb  = conv_b[d];
        float x0 = xs[0][d], x1 = xs[1][d], x2 = xs[2][d];
#pragma unroll
        for (int tt = 0; tt < 16; ++tt) {
            const float x3 = xs[tt + 3][d];
            float s = cw4.x*x0 + cw4.y*x1 + cw4.z*x2 + cw4.w*x3 + cb;
            g_xc[((size_t)(b*Tv + t0 + tt)) * DIv + d] = s / (1.f + __expf(-s));
            x0 = x1; x1 = x2; x2 = x3;
        }
    }
}

// ---------------------------------------------------------------------------
// x_proj GEMM (BM=32, BN=64) + dt_proj/softplus + B/C.
// grid (1, 256) -> full-wave coverage.  8 warps as 2(m) x 4(n),
// warp tile 16x16 (1 acc frag).  256 threads, 2 blocks/SM.
// ---------------------------------------------------------------------------
__global__ void __launch_bounds__(256, 2)
xproj_dt_kernel(const __nv_bfloat16* __restrict__ Whi,
                const __nv_bfloat16* __restrict__ Wlo,
                const float* __restrict__ dtw,
                const float* __restrict__ dtb)
{
    __shared__ __align__(16) __nv_bfloat16 Ah[32*SPAD];
    __shared__ __align__(16) __nv_bfloat16 Al[32*SPAD];
    __shared__ __align__(16) __nv_bfloat16 Bh[64*SPAD];
    __shared__ __align__(16) __nv_bfloat16 Bl[64*SPAD];
    __shared__ __align__(16) float xdbl_s[32][68];

    const int tid = threadIdx.x;
    const int bm  = blockIdx.y;           // 0..255 (32 rows each)
    const int wid = tid >> 5;
    const int wm  = wid >> 2;             // 0..1 -> 16 rows
    const int wn  = wid & 3;              // 0..3 -> 16 cols
    const int K   = DIv;

    wmma::fragment<wmma::accumulator, 16, 16, 16, float> acc;
    wmma::fill_fragment(acc, 0.0f);

    for (int k0 = 0; k0 < K; k0 += 32) {
        // stage A: 32 rows x 32 floats = 256 float4s (1 per thread)
        {
            const int row = tid >> 3;
            const int kc  = (tid & 7) << 2;
            const float4 v = *(const float4*)(g_xc + (size_t)(bm*32 + row) * K + k0 + kc);
            __nv_bfloat16 h0 = __float2bfloat16(v.x);
            __nv_bfloat16 h1 = __float2bfloat16(v.y);
            __nv_bfloat16 h2 = __float2bfloat16(v.z);
            __nv_bfloat16 h3 = __float2bfloat16(v.w);
            __nv_bfloat162 ph0; ph0.x = h0; ph0.y = h1;
            __nv_bfloat162 ph1; ph1.x = h2; ph1.y = h3;
            *(__nv_bfloat162*)(Ah + row*SPAD + kc)     = ph0;
            *(__nv_bfloat162*)(Ah + row*SPAD + kc + 2) = ph1;
            __nv_bfloat162 pl0; pl0.x = __float2bfloat16(v.x - __bfloat162float(h0));
                                pl0.y = __float2bfloat16(v.y - __bfloat162float(h1));
            __nv_bfloat162 pl1; pl1.x = __float2bfloat16(v.z - __bfloat162float(h2));
                                pl1.y = __float2bfloat16(v.w - __bfloat162float(h3));
            *(__nv_bfloat162*)(Al + row*SPAD + kc)     = pl0;
            *(__nv_bfloat162*)(Al + row*SPAD + kc + 2) = pl1;
        }
        // stage W: 64 rows x 32 halves = 256 float4s (1 per thread)
        {
            const int row = tid >> 2;
            const int kc  = (tid & 3) << 3;
            const size_t g = (size_t)row * K + k0 + kc;
            *(float4*)(Bh + row*SPAD + kc) = *(const float4*)(Whi + g);
            *(float4*)(Bl + row*SPAD + kc) = *(const float4*)(Wlo + g);
        }
        __syncthreads();

#pragma unroll
        for (int ks = 0; ks < 32; ks += 16) {
            wmma::fragment<wmma::matrix_b, 16, 16, 16, __nv_bfloat16, wmma::col_major> bH, bL;
            wmma::load_matrix_sync(bH, Bh + (wn*16)*SPAD + ks, SPAD);
            wmma::load_matrix_sync(bL, Bl + (wn*16)*SPAD + ks, SPAD);
            wmma::fragment<wmma::matrix_a, 16, 16, 16, __nv_bfloat16, wmma::row_major> aH, aL;
            wmma::load_matrix_sync(aH, Ah + (wm*16)*SPAD + ks, SPAD);
            wmma::load_matrix_sync(aL, Al + (wm*16)*SPAD + ks, SPAD);
            wmma::mma_sync(acc, aH, bH, acc);
            wmma::mma_sync(acc, aH, bL, acc);
            wmma::mma_sync(acc, aL, bH, acc);
        }
        __syncthreads();
    }

    // epilogue: xdbl tile -> smem
    wmma::store_matrix_sync(&xdbl_s[wm*16][wn*16], acc, 68, wmma::mem_row_major);
    __syncthreads();

    const int row0 = bm * 32;    // 32 | 1024: never crosses batch boundary

    // B/C extraction: 32 rows x 32 cols = 1024 over 256 threads
    {
        int idx = tid;
#pragma unroll
        for (int r = 0; r < 4; ++r, idx += 256) {
            const int tt = idx >> 5, c = idx & 31;
            g_BC[((size_t)(row0 + tt)) * (2*Nv) + c] = xdbl_s[tt][16 + c];
        }
    }

    // dt_proj + softplus: 2 channels/thread across 32 rows
    {
        const int d0 = tid, d1 = tid + 256;
        float w0[16], w1[16];
        *(float4*)&w0[0]  = *(const float4*)(dtw + d0*16 + 0);
        *(float4*)&w0[4]  = *(const float4*)(dtw + d0*16 + 4);
        *(float4*)&w0[8]  = *(const float4*)(dtw + d0*16 + 8);
        *(float4*)&w0[12] = *(const float4*)(dtw + d0*16 + 12);
        *(float4*)&w1[0]  = *(const float4*)(dtw + d1*16 + 0);
        *(float4*)&w1[4]  = *(const float4*)(dtw + d1*16 + 4);
        *(float4*)&w1[8]  = *(const float4*)(dtw + d1*16 + 8);
        *(float4*)&w1[12] = *(const float4*)(dtw + d1*16 + 12);
        const float b0 = dtb[d0], b1 = dtb[d1];

        for (int r = 0; r < 32; ++r) {
            float xv[16];
            *(float4*)&xv[0]  = *(const float4*)&xdbl_s[r][0];
            *(float4*)&xv[4]  = *(const float4*)&xdbl_s[r][4];
            *(float4*)&xv[8]  = *(const float4*)&xdbl_s[r][8];
            *(float4*)&xv[12] = *(const float4*)&xdbl_s[r][12];
            float s0 = b0, s1 = b1;
#pragma unroll
            for (int k = 0; k < 16; ++k) {
                s0 += xv[k] * w0[k];
                s1 += xv[k] * w1[k];
            }
            const float sp0 = fmaxf(s0, 0.f) + log1pf(__expf(-fabsf(s0)));
            const float sp1 = fmaxf(s1, 0.f) + log1pf(__expf(-fabsf(s1)));
            const size_t o = ((size_t)(row0 + r)) * DIv;
            g_dt[o + d0] = sp0;
            g_dt[o + d1] = sp1;
        }
    }
}

// ---------------------------------------------------------------------------
// Scan v3 pass 1 (unchanged).  grid (4, 8, 7), 128 threads.
// ---------------------------------------------------------------------------
__global__ void __launch_bounds__(128)
scan_pass1_kernel(const float* __restrict__ A_log)
{
    __shared__ __align__(16) float s_b[64][16];

    const int tid = threadIdx.x;
    const int d   = blockIdx.x * 128 + tid;
    const int b   = blockIdx.y;
    const int ch  = blockIdx.z;

    float a[16];
    {
        float4 v0 = *(const float4*)(A_log + d*16 + 0);
        float4 v1 = *(const float4*)(A_log + d*16 + 4);
        float4 v2 = *(const float4*)(A_log + d*16 + 8);
        float4 v3 = *(const float4*)(A_log + d*16 + 12);
        a[0]=-__expf(v0.x); a[1]=-__expf(v0.y); a[2]=-__expf(v0.z); a[3]=-__expf(v0.w);
        a[4]=-__expf(v1.x); a[5]=-__expf(v1.y); a[6]=-__expf(v1.z); a[7]=-__expf(v1.w);
        a[8]=-__expf(v2.x); a[9]=-__expf(v2.y); a[10]=-__expf(v2.z); a[11]=-__expf(v2.w);
        a[12]=-__expf(v3.x); a[13]=-__expf(v3.y); a[14]=-__expf(v3.z); a[15]=-__expf(v3.w);
    }

    float h[16], P[16];
#pragma unroll
    for (int n = 0; n < 16; ++n) { h[n] = 0.f; P[n] = 1.f; }

    for (int sc = 0; sc < 2; ++sc) {
        const int base = b * Tv + ch * CHT + sc * 64;
#pragma unroll
        for (int i = 0; i < 8; ++i) {
            const int idx = tid + i * 128;
            const int t = idx >> 4, n = idx & 15;
            s_b[t][n] = g_BC[(size_t)(base + t) * (2*Nv) + n];
        }
        __syncthreads();

#pragma unroll 2
        for (int t = 0; t < 64; ++t) {
            const float dtv = g_dt[(size_t)(base + t) * DIv + d];
            const float uv  = g_xc[(size_t)(base + t) * DIv + d];
            const float dtu = dtv * uv;
            const float4 B0 = *(const float4*)&s_b[t][0];
            const float4 B1 = *(const float4*)&s_b[t][4];
            const float4 B2 = *(const float4*)&s_b[t][8];
            const float4 B3 = *(const float4*)&s_b[t][12];
            const float Bs[16] = {B0.x,B0.y,B0.z,B0.w, B1.x,B1.y,B1.z,B1.w,
                                  B2.x,B2.y,B2.z,B2.w, B3.x,B3.y,B3.z,B3.w};
#pragma unroll
            for (int n = 0; n < 16; ++n) {
                const float e = __expf(dtv * a[n]);
                h[n] = e * h[n] + dtu * Bs[n];
                P[n] *= e;
            }
        }
        __syncthreads();
    }

    const size_t o = (((size_t)b * DIv + d) * Nv) * NCH + ch;
#pragma unroll
    for (int n = 0; n < 16; ++n) {
        g_chP[o + n*NCH] = P[n];
        g_chH[o + n*NCH] = h[n];
    }
}

// ---------------------------------------------------------------------------
// Scan v3 pass 2 (unchanged).  grid (4, 8, 8), 128 threads.
// ---------------------------------------------------------------------------
__global__ void __launch_bounds__(128)
scan_pass2_kernel(const float* __restrict__ A_log, const float* __restrict__ Dp)
{
    __shared__ __align__(16) float s_bc[64][32];

    const int tid = threadIdx.x;
    const int d   = blockIdx.x * 128 + tid;
    const int b   = blockIdx.y;
    const int ch  = blockIdx.z;

    float a[16];
    {
        float4 v0 = *(const float4*)(A_log + d*16 + 0);
        float4 v1 = *(const float4*)(A_log + d*16 + 4);
        float4 v2 = *(const float4*)(A_log + d*16 + 8);
        float4 v3 = *(const float4*)(A_log + d*16 + 12);
        a[0]=-__expf(v0.x); a[1]=-__expf(v0.y); a[2]=-__expf(v0.z); a[3]=-__expf(v0.w);
        a[4]=-__expf(v1.x); a[5]=-__expf(v1.y); a[6]=-__expf(v1.z); a[7]=-__expf(v1.w);
        a[8]=-__expf(v2.x); a[9]=-__expf(v2.y); a[10]=-__expf(v2.z); a[11]=-__expf(v2.w);
        a[12]=-__expf(v3.x); a[13]=-__expf(v3.y); a[14]=-__expf(v3.z); a[15]=-__expf(v3.w);
    }
    const float dcoef = Dp[d];

    float h[16];
    {
        const size_t sb = (((size_t)b * DIv + d) * Nv) * NCH;
#pragma unroll
        for (int n = 0; n < 16; ++n) {
            float hh = 0.f;
            for (int c = 0; c < ch; ++c)
                hh = g_chP[sb + n*NCH + c] * hh + g_chH[sb + n*NCH + c];
            h[n] = hh;
        }
    }

    for (int sc = 0; sc < 2; ++sc) {
        const int base = b * Tv + ch * CHT + sc * 64;
#pragma unroll
        for (int i = 0; i < 16; ++i) {
            const int idx = tid + i * 128;
            const int t = idx >> 5, c = idx & 31;
            s_bc[t][c] = g_BC[(size_t)(base + t) * (2*Nv) + c];
        }
        __syncthreads();

#pragma unroll 2
        for (int t = 0; t < 64; ++t) {
            const float dtv = g_dt[(size_t)(base + t) * DIv + d];
            const float uv  = g_xc[(size_t)(base + t) * DIv + d];
            const float zv  = g_xz[(size_t)(base + t) * (2*DIv) + DIv + d];
            const float dtu = dtv * uv;
            const float4 B0 = *(const float4*)&s_bc[t][0];
            const float4 B1 = *(const float4*)&s_bc[t][4];
            const float4 B2 = *(const float4*)&s_bc[t][8];
            const float4 B3 = *(const float4*)&s_bc[t][12];
            const float4 C0 = *(const float4*)&s_bc[t][16];
            const float4 C1 = *(const float4*)&s_bc[t][20];
            const float4 C2 = *(const float4*)&s_bc[t][24];
            const float4 C3 = *(const float4*)&s_bc[t][28];
            const float Bs[16] = {B0.x,B0.y,B0.z,B0.w, B1.x,B1.y,B1.z,B1.w,
                                  B2.x,B2.y,B2.z,B2.w, B3.x,B3.y,B3.z,B3.w};
            const float Cs[16] = {C0.x,C0.y,C0.z,C0.w, C1.x,C1.y,C1.z,C1.w,
                                  C2.x,C2.y,C2.z,C2.w, C3.x,C3.y,C3.z,C3.w};
            float y = 0.f;
#pragma unroll
            for (int n = 0; n < 16; ++n) {
                const float e = __expf(dtv * a[n]);
                h[n] = e * h[n] + dtu * Bs[n];
                y += h[n] * Cs[n];
            }
            y += dcoef * uv;
            y *= zv / (1.f + __expf(-zv));
            g_y[(size_t)(base + t) * DIv + d] = y;
        }
        __syncthreads();
    }
}

// ---------------------------------------------------------------------------
// Final: LayerNorm(last token) + head.
// ---------------------------------------------------------------------------
__global__ void __launch_bounds__(256)
final_kernel(const float* __restrict__ ln_g, const float* __restrict__ ln_b,
             const float* __restrict__ head_w, const float* __restrict__ head_b,
             float* __restrict__ out)
{
    __shared__ float red[256];
    const int b = blockIdx.x, tid = threadIdx.x;
    const float v = g_h[((size_t)(b * Tv + (Tv - 1))) * DMv + tid];

    red[tid] = v; __syncthreads();
    for (int s = 128; s > 0; s >>= 1) { if (tid < s) red[tid] += red[tid + s]; __syncthreads(); }
    const float mu = red[0] * (1.f / DMv);
    __syncthreads();

    const float dv = v - mu;
    red[tid] = dv * dv; __syncthreads();
    for (int s = 128; s > 0; s >>= 1) { if (tid < s) red[tid] += red[tid + s]; __syncthreads(); }
    const float var = red[0] * (1.f / DMv);
    __syncthreads();

    const float hn = dv * rsqrtf(var + 1e-5f) * ln_g[tid] + ln_b[tid];
    red[tid] = hn * head_w[tid]; __syncthreads();
    for (int s = 128; s > 0; s >>= 1) { if (tid < s) red[tid] += red[tid + s]; __syncthreads(); }
    if (tid == 0) out[b] = red[0] + head_b[0];
}

// ---------------------------------------------------------------------------
// Host launcher
// ---------------------------------------------------------------------------
extern "C" void kernel_launch(void* const* d_in, const int* in_sizes, int n_in,
                              void* d_out, int out_size)
{
    const float* x      = (const float*)d_in[0];
    const float* proj_w = (const float*)d_in[1];
    const float* proj_b = (const float*)d_in[2];
    const float* ipw    = (const float*)d_in[3];
    const float* cw     = (const float*)d_in[4];
    const float* cb     = (const float*)d_in[5];
    const float* xpw    = (const float*)d_in[6];
    const float* dtw    = (const float*)d_in[7];
    const float* dtb    = (const float*)d_in[8];
    const float* A_log  = (const float*)d_in[9];
    const float* Dp     = (const float*)d_in[10];
    const float* opw    = (const float*)d_in[11];
    const float* ln_g   = (const float*)d_in[12];
    const float* ln_b   = (const float*)d_in[13];
    const float* head_w = (const float*)d_in[14];
    const float* head_b = (const float*)d_in[15];
    float* out = (float*)d_out;

    float *hbuf, *xzbuf, *ybuf;
    __nv_bfloat16 *whi, *wlo;
    cudaGetSymbolAddress((void**)&hbuf,  g_h);
    cudaGetSymbolAddress((void**)&xzbuf, g_xz);
    cudaGetSymbolAddress((void**)&ybuf,  g_y);
    cudaGetSymbolAddress((void**)&whi,   g_whi);
    cudaGetSymbolAddress((void**)&wlo,   g_wlo);

    // Launch 1: all weight splits.
    split_all_kernel<<<1680, 256>>>(proj_w, ipw, opw, xpw, whi, wlo);

    dim3 grid_in(2, 128);
    dim3 grid_ip(8, 64);
    dim3 grid_op(2, 128);
    dim3 grid_xp(1, 256);     // BM=32 -> 256 blocks, full-wave
    dim3 grid_p1(4, 8, 7);
    dim3 grid_p2(4, 8, 8);

    // Launch 2: input projection  h = x @ proj_w^T  [8192,256], K=64
    wgemm_nt_kernel<<<grid_in, 256>>>(x, (const float*)0,
                                      whi + W_PROJ, wlo + W_PROJ,
                                      hbuf, BT, DMv, Fv);

    for (int l = 0; l < Lv; ++l) {
        const size_t ipoff = (size_t)l * 262144;
        const size_t opoff = (size_t)l * 131072;
        const size_t xpoff = (size_t)l * 32768;
        const float* abias  = (l == 0) ? proj_b : (const float*)0;
        const float* alog_l = A_log + (size_t)l * DIv * Nv;

        // in_proj (big-tile): xz = (h+bias?) @ ipw^T  [8192,1024], K=256
        wgemm_ip_kernel<<<grid_ip, 256>>>(hbuf, abias,
                                          whi + W_IPW + ipoff, wlo + W_IPW + ipoff,
                                          xzbuf, BT, 2*DIv, DMv);

        // Launch 4 (profiled, l==0): conv + SiLU v3
        conv_silu_kernel<<<512, 256>>>(cw + (size_t)l * DIv * DCv,
                                       cb + (size_t)l * DIv);

        // x_proj GEMM + dt_proj + B/C (BM=32, full-wave grid)
        xproj_dt_kernel<<<grid_xp, 256>>>(whi + W_XPW + xpoff,
                                          wlo + W_XPW + xpoff,
                                          dtw + (size_t)l * DIv * DTRv,
                                          dtb + (size_t)l * DIv);

        scan_pass1_kernel<<<grid_p1, 128>>>(alog_l);
        scan_pass2_kernel<<<grid_p2, 128>>>(alog_l, Dp + (size_t)l * DIv);

        // out_proj: h = y @ opw^T   [8192,256], K=512
        wgemm_nt_kernel<<<grid_op, 256>>>(ybuf, (const float*)0,
                                          whi + W_OPW + opoff, wlo + W_OPW + opoff,
                                          hbuf, BT, DMv, DIv);
    }

    final_kernel<<<Bv, 256>>>(ln_g, ln_b, head_w, head_b, out);
}